// round 4
// baseline (speedup 1.0000x reference)
#include <cuda_runtime.h>

// out[0:100]   = Xp[inds1[m,0], inds1[m,1]] = dot(I[row,:], p)
// out[100:200] = Yp[inds2[m,0], inds2[m,1]] = dot(J[row,:], p)
// row = ind[0]*28 + ind[1], P = 50000.
// Split-K: each of the 200 dot products is computed by SPLIT blocks over
// disjoint chunks of the 50000-dim, partials reduced by a tiny second kernel.

#define P_DIM    50000
#define P_VEC4   (P_DIM / 4)       // 12500 float4 per row
#define SPLIT    4
#define CHUNK4   (P_VEC4 / SPLIT)  // 3125 float4 per block
#define CARD2    100
#define NOUT     (2 * CARD2)       // 200
#define W_IMG    28
#define NTHREADS 512
#define NWARPS   (NTHREADS / 32)

__device__ float g_partials[NOUT * SPLIT];

__global__ __launch_bounds__(NTHREADS)
void gather_dot_partial(const float* __restrict__ p,
                        const float* __restrict__ I,
                        const float* __restrict__ J,
                        const int*   __restrict__ inds1,
                        const int*   __restrict__ inds2)
{
    const int m     = blockIdx.x;   // 0..199  output index
    const int chunk = blockIdx.y;   // 0..SPLIT-1

    const float* mat;
    const int*   ind;
    if (m < CARD2) { mat = I; ind = inds1 + 2 * m; }
    else           { mat = J; ind = inds2 + 2 * (m - CARD2); }

    const int row = ind[0] * W_IMG + ind[1];

    const float4* __restrict__ rp =
        reinterpret_cast<const float4*>(mat + (size_t)row * P_DIM) + chunk * CHUNK4;
    const float4* __restrict__ pp =
        reinterpret_cast<const float4*>(p) + chunk * CHUNK4;

    // 3125 float4 per block / 512 threads -> up to 7 iterations.
    // Unroll by 2 for MLP (4 independent 16B loads in flight per thread).
    float sum = 0.0f;
    int i = threadIdx.x;
    #pragma unroll 2
    for (; i + NTHREADS < CHUNK4; i += 2 * NTHREADS) {
        float4 a0 = rp[i];
        float4 b0 = pp[i];
        float4 a1 = rp[i + NTHREADS];
        float4 b1 = pp[i + NTHREADS];
        sum += a0.x * b0.x + a0.y * b0.y + a0.z * b0.z + a0.w * b0.w;
        sum += a1.x * b1.x + a1.y * b1.y + a1.z * b1.z + a1.w * b1.w;
    }
    if (i < CHUNK4) {
        float4 a = rp[i];
        float4 b = pp[i];
        sum += a.x * b.x + a.y * b.y + a.z * b.z + a.w * b.w;
    }

    // Warp reduction
    #pragma unroll
    for (int off = 16; off > 0; off >>= 1)
        sum += __shfl_xor_sync(0xFFFFFFFFu, sum, off);

    __shared__ float warp_sums[NWARPS];
    const int lane = threadIdx.x & 31;
    const int wid  = threadIdx.x >> 5;
    if (lane == 0) warp_sums[wid] = sum;
    __syncthreads();

    if (wid == 0) {
        float v = (lane < NWARPS) ? warp_sums[lane] : 0.0f;
        #pragma unroll
        for (int off = NWARPS / 2; off > 0; off >>= 1)
            v += __shfl_xor_sync(0xFFFFFFFFu, v, off);
        if (lane == 0) g_partials[m * SPLIT + chunk] = v;
    }
}

__global__ __launch_bounds__(NOUT)
void reduce_partials(float* __restrict__ out)
{
    const int m = threadIdx.x;   // single block, 200 threads
    float s = 0.0f;
    #pragma unroll
    for (int c = 0; c < SPLIT; c++)
        s += g_partials[m * SPLIT + c];
    out[m] = s;
}

extern "C" void kernel_launch(void* const* d_in, const int* in_sizes, int n_in,
                              void* d_out, int out_size)
{
    const float* p     = (const float*)d_in[0];   // [50000]
    const float* I     = (const float*)d_in[1];   // [784, 50000]
    const float* J     = (const float*)d_in[2];   // [784, 50000]
    const int*   inds1 = (const int*)  d_in[3];   // [100, 2]
    const int*   inds2 = (const int*)  d_in[4];   // [100, 2]
    float*       out   = (float*)d_out;           // [200]

    dim3 grid(NOUT, SPLIT);
    gather_dot_partial<<<grid, NTHREADS>>>(p, I, J, inds1, inds2);
    reduce_partials<<<1, NOUT>>>(out);
}

// round 5
// speedup vs baseline: 1.2113x; 1.2113x over previous
#include <cuda_runtime.h>

// out[0:100]   = dot(I[row1_m,:], p),  row = ind[0]*28 + ind[1]
// out[100:200] = dot(J[row2_m,:], p),  P = 50000.
//
// Single-kernel split-K:
//   - 100 row-pairs (m0=2q, m1=2q+1) x SPLIT=6 chunks = 600 blocks
//     (600*512 threads ~= exactly one full wave on 148 SMs @ 2048 thr/SM)
//   - each block: 2 rows share one p-chunk load (halves p re-read traffic)
//   - partials to __device__ scratch; LAST finishing block (atomic ticket)
//     does the deterministic final reduction and resets the ticket.

#define P_DIM     50000
#define P_VEC4    (P_DIM / 4)     // 12500 float4 per row
#define SPLIT     6
#define CARD2     100
#define NOUT      (2 * CARD2)     // 200
#define NPAIRS    (NOUT / 2)      // 100
#define NBLOCKS   (NPAIRS * SPLIT) // 600
#define W_IMG     28
#define NTHREADS  512
#define NWARPS    (NTHREADS / 32)

__device__ float        g_partials[NOUT * SPLIT];
__device__ unsigned int g_ticket = 0;

// chunk c covers float4 indices [c*2083 + min(c,2), next) ; sizes 2084,2084,2083x4
__device__ __forceinline__ int chunk_start(int c) { return c * 2083 + (c < 2 ? c : 2); }

__global__ __launch_bounds__(NTHREADS, 4)
void gather_dot_fused(const float* __restrict__ p,
                      const float* __restrict__ I,
                      const float* __restrict__ J,
                      const int*   __restrict__ inds1,
                      const int*   __restrict__ inds2,
                      float*       __restrict__ out)
{
    const int pair  = blockIdx.x / SPLIT;   // 0..99
    const int chunk = blockIdx.x % SPLIT;   // 0..5
    const int m0 = 2 * pair;                // both m's in same matrix (pair<50 -> I)
    const int m1 = m0 + 1;

    const float* mat;
    const int*   ind;
    if (m0 < CARD2) { mat = I; ind = inds1 + 2 * m0; }
    else            { mat = J; ind = inds2 + 2 * (m0 - CARD2); }

    const int row0 = ind[0] * W_IMG + ind[1];
    const int row1 = ind[2] * W_IMG + ind[3];

    const int c0 = chunk_start(chunk);
    const int c1 = chunk_start(chunk + 1);

    const float4* __restrict__ r0 =
        reinterpret_cast<const float4*>(mat + (size_t)row0 * P_DIM);
    const float4* __restrict__ r1 =
        reinterpret_cast<const float4*>(mat + (size_t)row1 * P_DIM);
    const float4* __restrict__ pp = reinterpret_cast<const float4*>(p);

    float sum0 = 0.0f, sum1 = 0.0f;
    #pragma unroll 2
    for (int i = c0 + threadIdx.x; i < c1; i += NTHREADS) {
        float4 pv = pp[i];
        float4 a0 = r0[i];
        float4 a1 = r1[i];
        sum0 += a0.x * pv.x + a0.y * pv.y + a0.z * pv.z + a0.w * pv.w;
        sum1 += a1.x * pv.x + a1.y * pv.y + a1.z * pv.z + a1.w * pv.w;
    }

    // Warp reduction (both sums)
    #pragma unroll
    for (int off = 16; off > 0; off >>= 1) {
        sum0 += __shfl_xor_sync(0xFFFFFFFFu, sum0, off);
        sum1 += __shfl_xor_sync(0xFFFFFFFFu, sum1, off);
    }

    __shared__ float warp_sums0[NWARPS];
    __shared__ float warp_sums1[NWARPS];
    __shared__ bool  s_last;
    const int lane = threadIdx.x & 31;
    const int wid  = threadIdx.x >> 5;
    if (lane == 0) { warp_sums0[wid] = sum0; warp_sums1[wid] = sum1; }
    __syncthreads();

    if (wid == 0) {
        float v0 = (lane < NWARPS) ? warp_sums0[lane] : 0.0f;
        float v1 = (lane < NWARPS) ? warp_sums1[lane] : 0.0f;
        #pragma unroll
        for (int off = NWARPS / 2; off > 0; off >>= 1) {
            v0 += __shfl_xor_sync(0xFFFFFFFFu, v0, off);
            v1 += __shfl_xor_sync(0xFFFFFFFFu, v1, off);
        }
        if (lane == 0) {
            g_partials[m0 * SPLIT + chunk] = v0;
            g_partials[m1 * SPLIT + chunk] = v1;
        }
    }

    // Make partials visible, then take a ticket. The last block reduces.
    __threadfence();
    if (threadIdx.x == 0) {
        unsigned int t = atomicAdd(&g_ticket, 1u);
        s_last = (t == NBLOCKS - 1);
    }
    __syncthreads();

    if (s_last) {
        const int m = threadIdx.x;
        if (m < NOUT) {
            float s = 0.0f;
            #pragma unroll
            for (int c = 0; c < SPLIT; c++)
                s += __ldcg(&g_partials[m * SPLIT + c]);  // bypass L1: cross-SM data
            out[m] = s;
        }
        if (threadIdx.x == 0) g_ticket = 0;   // reset for next (deterministic) call
    }
}

extern "C" void kernel_launch(void* const* d_in, const int* in_sizes, int n_in,
                              void* d_out, int out_size)
{
    const float* p     = (const float*)d_in[0];   // [50000]
    const float* I     = (const float*)d_in[1];   // [784, 50000]
    const float* J     = (const float*)d_in[2];   // [784, 50000]
    const int*   inds1 = (const int*)  d_in[3];   // [100, 2]
    const int*   inds2 = (const int*)  d_in[4];   // [100, 2]
    float*       out   = (float*)d_out;           // [200]

    gather_dot_fused<<<NBLOCKS, NTHREADS>>>(p, I, J, inds1, inds2, out);
}